// round 15
// baseline (speedup 1.0000x reference)
#include <cuda_runtime.h>
#include <cuda_bf16.h>
#include <math.h>
#include <stdint.h>

#define NB   4
#define CIN  256
#define C8D  32
#define NPIX 4096

// Scratch (device globals: allocation-free per harness rules).
__device__ float g_q[NB * C8D * NPIX];          // tf32-rounded
__device__ float g_k[NB * C8D * NPIX];          // tf32-rounded
__device__ __nv_bfloat16 g_v[NB * CIN * NPIX];  // bf16

__device__ __forceinline__ unsigned f2tf32(float x) {
    unsigned u;
    asm("cvt.rna.tf32.f32 %0, %1;" : "=r"(u) : "f"(x));
    return u;
}

__device__ __forceinline__ void mma_tf32(float* d, const unsigned* a, const unsigned* b) {
    asm volatile(
        "mma.sync.aligned.m16n8k8.row.col.f32.tf32.tf32.f32 "
        "{%0,%1,%2,%3}, {%4,%5,%6,%7}, {%8,%9}, {%0,%1,%2,%3};"
        : "+f"(d[0]), "+f"(d[1]), "+f"(d[2]), "+f"(d[3])
        : "r"(a[0]), "r"(a[1]), "r"(a[2]), "r"(a[3]), "r"(b[0]), "r"(b[1]));
}

__device__ __forceinline__ void mma_bf16(float* d, const unsigned* a, unsigned b0, unsigned b1) {
    asm volatile(
        "mma.sync.aligned.m16n8k16.row.col.f32.bf16.bf16.f32 "
        "{%0,%1,%2,%3}, {%4,%5,%6,%7}, {%8,%9}, {%0,%1,%2,%3};"
        : "+f"(d[0]), "+f"(d[1]), "+f"(d[2]), "+f"(d[3])
        : "r"(a[0]), "r"(a[1]), "r"(a[2]), "r"(a[3]), "r"(b0), "r"(b1));
}

__device__ __forceinline__ unsigned pack_bf16(float lo, float hi) {
    __nv_bfloat162 p = __floats2bfloat162_rn(lo, hi);
    return *(unsigned*)&p;
}

__device__ __forceinline__ void cp16(unsigned dst, const void* src) {
    asm volatile("cp.async.cg.shared.global [%0], [%1], 16;\n" :: "r"(dst), "l"(src));
}

__device__ __forceinline__ void ldsm_x4(unsigned& r0, unsigned& r1, unsigned& r2, unsigned& r3,
                                        unsigned addr) {
    asm volatile("ldmatrix.sync.aligned.m8n8.x4.shared.b16 {%0,%1,%2,%3}, [%4];"
                 : "=r"(r0), "=r"(r1), "=r"(r2), "=r"(r3) : "r"(addr));
}

// ---------------------------------------------------------------------------
// Merged projection GEMM on tf32 mma (unchanged — measured ~27us).
// ---------------------------------------------------------------------------
#define PW_S 36
#define PX_S 136
#define P_WBUF (64 * PW_S * 4)
#define P_XOFF (2 * P_WBUF)
#define P_XBUF (32 * PX_S * 4)
#define P_TOTAL (P_XOFF + 2 * P_XBUF)

__global__ __launch_bounds__(256) void proj_kernel(
    const float* __restrict__ x,
    const float* __restrict__ Wq, const float* __restrict__ bq,
    const float* __restrict__ Wk, const float* __restrict__ bk,
    const float* __restrict__ Wv, const float* __restrict__ bv)
{
    extern __shared__ char smc[];
    unsigned sm_base = (unsigned)__cvta_generic_to_shared(smc);

    int b  = blockIdx.z;
    int r0 = blockIdx.y * 64;
    int n0 = blockIdx.x * 128;
    int t  = threadIdx.x;
    int w = t >> 5, lane = t & 31;
    int g = lane >> 2, t4 = lane & 3;
    int wr = w & 3, wc = w >> 2;
    const float* xb = x + ((size_t)b * CIN) * NPIX;

    auto wrow = [&](int gr) -> const float* {
        return (gr < 256) ? (Wv + (size_t)gr * 256)
             : (gr < 288) ? (Wq + (size_t)(gr - 256) * 256)
                          : (Wk + (size_t)(gr - 288) * 256);
    };

    auto issue_stage = [&](int ch) {
        int k0 = ch * 32;
        unsigned wdst = sm_base + (unsigned)(ch & 1) * P_WBUF;
#pragma unroll
        for (int i = 0; i < 2; i++) {
            int idx = t + 256 * i;
            int row = idx >> 3, seg = idx & 7;
            cp16(wdst + (unsigned)(row * PW_S + seg * 4) * 4,
                 wrow(r0 + row) + k0 + seg * 4);
        }
        unsigned xdst = sm_base + P_XOFF + (unsigned)(ch & 1) * P_XBUF;
#pragma unroll
        for (int i = 0; i < 4; i++) {
            int idx = t + 256 * i;
            int row = idx >> 5, seg = idx & 31;
            cp16(xdst + (unsigned)(row * PX_S + seg * 4) * 4,
                 xb + (size_t)(k0 + row) * NPIX + n0 + seg * 4);
        }
        asm volatile("cp.async.commit_group;\n");
    };

    issue_stage(0);

    float acc[8][4];
#pragma unroll
    for (int jb = 0; jb < 8; jb++)
#pragma unroll
        for (int q = 0; q < 4; q++) acc[jb][q] = 0.0f;

    for (int ch = 0; ch < 8; ch++) {
        asm volatile("cp.async.wait_group 0;\n");
        __syncthreads();
        if (ch + 1 < 8) issue_stage(ch + 1);

        const unsigned* Wu = (const unsigned*)(smc + (ch & 1) * P_WBUF);
        const unsigned* Xu = (const unsigned*)(smc + P_XOFF + (ch & 1) * P_XBUF);

#pragma unroll
        for (int ks = 0; ks < 4; ks++) {
            int kk = 8 * ks;
            unsigned a[4];
            a[0] = Wu[(16 * wr + g)     * PW_S + kk + t4];
            a[1] = Wu[(16 * wr + g + 8) * PW_S + kk + t4];
            a[2] = Wu[(16 * wr + g)     * PW_S + kk + t4 + 4];
            a[3] = Wu[(16 * wr + g + 8) * PW_S + kk + t4 + 4];
#pragma unroll
            for (int jb = 0; jb < 8; jb++) {
                unsigned bfr[2];
                bfr[0] = Xu[(kk + t4)     * PX_S + 64 * wc + 8 * jb + g];
                bfr[1] = Xu[(kk + t4 + 4) * PX_S + 64 * wc + 8 * jb + g];
                mma_tf32(acc[jb], a, bfr);
            }
        }
        __syncthreads();
    }

    int gr0 = r0 + 16 * wr + g;
    int gr1 = gr0 + 8;
#pragma unroll
    for (int half = 0; half < 2; half++) {
        int gr = half ? gr1 : gr0;
        if (gr < 256) {
            float bias = bv[gr];
            __nv_bfloat16* op = g_v + ((size_t)b * CIN + gr) * NPIX;
#pragma unroll
            for (int jb = 0; jb < 8; jb++) {
                int c0 = n0 + 64 * wc + 8 * jb + 2 * t4;
                float d0 = acc[jb][half ? 2 : 0] + bias;
                float d1 = acc[jb][half ? 3 : 1] + bias;
                *(unsigned*)&op[c0] = pack_bf16(d0, d1);
            }
        } else {
            float bias;
            float* op;
            if (gr < 288) { bias = bq[gr - 256]; op = g_q + ((size_t)b * C8D + gr - 256) * NPIX; }
            else          { bias = bk[gr - 288]; op = g_k + ((size_t)b * C8D + gr - 288) * NPIX; }
#pragma unroll
            for (int jb = 0; jb < 8; jb++) {
                int c0 = n0 + 64 * wc + 8 * jb + 2 * t4;
                float2 o;
                o.x = __uint_as_float(f2tf32(acc[jb][half ? 2 : 0] + bias));
                o.y = __uint_as_float(f2tf32(acc[jb][half ? 3 : 1] + bias));
                *(float2*)&op[c0] = o;
            }
        }
    }
}

// ---------------------------------------------------------------------------
// Flash attention, 4r x 4h tile (R14) + TWO key-tiles per barrier window:
// 32 windows x 128 keys. Window: S_A,exp_A,publish_A(set0), ownPV_A,
// S_B,exp_B,publish_B(set1), ONE named bar (covers both publishes),
// partnerPV_A, ownPV_B, partnerPV_B. 1 syncthreads + 1 named bar / 2 tiles.
// K x4 / V x4 tile buffers, one cp.async group per window (pair of tiles).
// ---------------------------------------------------------------------------
#define KS_S 72   // floats
#define VS_S 72   // bf16 units (144 B per row)
#define SM_K_BUF  (32 * KS_S * 4)             // 9216 B
#define SM_V_OFF  (4 * SM_K_BUF)              // 36864
#define SM_V_BUF  (256 * VS_S * 2)            // 36864 B
#define SM_PX_OFF (SM_V_OFF + 4 * SM_V_BUF)   // 184320 (2 sets x 16384)
#define SM_LS_OFF (SM_PX_OFF + 32768)         // 217088
#define SM_TOTAL  (SM_LS_OFF + 2048)          // 219136 B (1 CTA/SM)

__global__ __launch_bounds__(512, 1) void attn_kernel(
    const float* __restrict__ x, const float* __restrict__ gamma,
    float* __restrict__ out)
{
    extern __shared__ char smc[];
    unsigned sm_base = (unsigned)__cvta_generic_to_shared(smc);

    int t = threadIdx.x;
    int w = t >> 5, lane = t & 31;
    int g = lane >> 2, t4 = lane & 3;
    int r = w & 3;        // query rows [32r, 32r+32)
    int h = w >> 2;       // c quarter AND key quarter
    int b = blockIdx.y;
    int n0 = blockIdx.x * 128;

    const float* qb = g_q + ((size_t)b * C8D) * NPIX;
    const float* kb = g_k + ((size_t)b * C8D) * NPIX;
    const __nv_bfloat16* vbb = g_v + ((size_t)b * CIN) * NPIX;

    // Issue a PAIR of tiles {2tp, 2tp+1} as one commit group.
    auto issue_pair = [&](int tp) {
#pragma unroll
        for (int tt = 0; tt < 2; tt++) {
            int tile = 2 * tp + tt;
            int m0 = tile * 64;
            unsigned kdst = sm_base + (unsigned)(tile & 3) * SM_K_BUF;
            {
                int d = t >> 4, seg = t & 15;
                cp16(kdst + (unsigned)(d * KS_S + seg * 4) * 4,
                     kb + (size_t)d * NPIX + m0 + seg * 4);
            }
            unsigned vdst = sm_base + SM_V_OFF + (unsigned)(tile & 3) * SM_V_BUF;
#pragma unroll
            for (int i = 0; i < 4; i++) {
                int flat = t + 512 * i;
                int c = flat >> 3, seg = flat & 7;
                cp16(vdst + (unsigned)(c * VS_S + seg * 8) * 2,
                     vbb + (size_t)c * NPIX + m0 + seg * 8);
            }
        }
        asm volatile("cp.async.commit_group;\n");
    };

    issue_pair(0);

    const int row0 = 32 * r + g;      // rowgroup 0 base; rowgroup 1 = +16

    // Q fragments (loop-invariant, 32 regs)
    unsigned qa[4][2][4];
#pragma unroll
    for (int ks = 0; ks < 4; ks++) {
        int d0 = 8 * ks + t4;
#pragma unroll
        for (int rg = 0; rg < 2; rg++) {
            int rr = row0 + 16 * rg;
            qa[ks][rg][0] = __float_as_uint(qb[(size_t)d0 * NPIX + n0 + rr]);
            qa[ks][rg][1] = __float_as_uint(qb[(size_t)d0 * NPIX + n0 + rr + 8]);
            qa[ks][rg][2] = __float_as_uint(qb[(size_t)(d0 + 4) * NPIX + n0 + rr]);
            qa[ks][rg][3] = __float_as_uint(qb[(size_t)(d0 + 4) * NPIX + n0 + rr + 8]);
        }
    }

    unsigned laneoff = (unsigned)((8 * (lane >> 4) + (lane & 7)) * (VS_S * 2)
                                  + ((lane >> 3) & 1) * 16);
    unsigned vlane_base = sm_base + SM_V_OFF + (unsigned)(h * 64 * VS_S * 2) + laneoff;

    uint4* px = (uint4*)(smc + SM_PX_OFF);
    int px_base = r * 4;

    float O[8][2][4];
#pragma unroll
    for (int cb = 0; cb < 8; cb++)
#pragma unroll
        for (int rg = 0; rg < 2; rg++)
#pragma unroll
            for (int q = 0; q < 4; q++) O[cb][rg][q] = 0.0f;

    float lr[2][2] = {{0.0f, 0.0f}, {0.0f, 0.0f}};

    // S + exp for one tile's K buffer -> pown (also accumulates lr)
    auto s_exp = [&](const unsigned* Ku, unsigned pown[2][4]) {
        float S[2][2][4];
#pragma unroll
        for (int rg = 0; rg < 2; rg++)
#pragma unroll
            for (int j = 0; j < 2; j++)
#pragma unroll
                for (int q = 0; q < 4; q++) S[rg][j][q] = 0.0f;
#pragma unroll
        for (int ks = 0; ks < 4; ks++) {
            int kk = 8 * ks;
#pragma unroll
            for (int j = 0; j < 2; j++) {
                int jj = 2 * h + j;
                unsigned bfr[2];
                bfr[0] = Ku[(kk + t4)     * KS_S + 8 * jj + g];
                bfr[1] = Ku[(kk + t4 + 4) * KS_S + 8 * jj + g];
#pragma unroll
                for (int rg = 0; rg < 2; rg++)
                    mma_tf32(S[rg][j], qa[ks][rg], bfr);
            }
        }
#pragma unroll
        for (int rg = 0; rg < 2; rg++) {
#pragma unroll
            for (int j = 0; j < 2; j++) {
                float p00 = __expf(S[rg][j][0]);
                float p01 = __expf(S[rg][j][1]);
                float p10 = __expf(S[rg][j][2]);
                float p11 = __expf(S[rg][j][3]);
                lr[rg][0] += p00 + p01;
                lr[rg][1] += p10 + p11;
                if (j == 0) {
                    pown[rg][0] = pack_bf16(p00, p01);
                    pown[rg][1] = pack_bf16(p10, p11);
                } else {
                    pown[rg][2] = pack_bf16(p00, p01);
                    pown[rg][3] = pack_bf16(p10, p11);
                }
            }
        }
    };

    auto own_pv = [&](unsigned vlane, const unsigned pown[2][4]) {
#pragma unroll
        for (int p = 0; p < 4; p++) {
            unsigned b0, b1, b2, b3;
            ldsm_x4(b0, b1, b2, b3,
                    vlane + (unsigned)(p * 16 * VS_S * 2) + (unsigned)(h * 32));
#pragma unroll
            for (int rg = 0; rg < 2; rg++) {
                mma_bf16(O[2 * p][rg],     pown[rg], b0, b1);
                mma_bf16(O[2 * p + 1][rg], pown[rg], b2, b3);
            }
        }
    };

    auto partner_pv = [&](unsigned vlane, int set) {
#pragma unroll
        for (int dk = 1; dk < 4; dk++) {
            int kc = (h + dk) & 3;
            uint4 pp0 = px[set * 1024 + ((px_base + kc) * 2 + 0) * 32 + lane];
            uint4 pp1 = px[set * 1024 + ((px_base + kc) * 2 + 1) * 32 + lane];
            unsigned pfr[2][4] = {
                {pp0.x, pp0.y, pp0.z, pp0.w},
                {pp1.x, pp1.y, pp1.z, pp1.w}
            };
#pragma unroll
            for (int p = 0; p < 4; p++) {
                unsigned b0, b1, b2, b3;
                ldsm_x4(b0, b1, b2, b3,
                        vlane + (unsigned)(p * 16 * VS_S * 2) + (unsigned)(kc * 32));
#pragma unroll
                for (int rg = 0; rg < 2; rg++) {
                    mma_bf16(O[2 * p][rg],     pfr[rg], b0, b1);
                    mma_bf16(O[2 * p + 1][rg], pfr[rg], b2, b3);
                }
            }
        }
    };

    for (int win = 0; win < 32; win++) {
        asm volatile("cp.async.wait_group 0;\n");
        __syncthreads();
        if (win + 1 < 32) issue_pair(win + 1);

        int tileA = 2 * win, tileB = 2 * win + 1;
        const unsigned* KuA = (const unsigned*)(smc + (tileA & 3) * SM_K_BUF);
        const unsigned* KuB = (const unsigned*)(smc + (tileB & 3) * SM_K_BUF);
        unsigned vlaneA = vlane_base + (unsigned)(tileA & 3) * SM_V_BUF;
        unsigned vlaneB = vlane_base + (unsigned)(tileB & 3) * SM_V_BUF;

        // --- tile A: S, exp, publish (set 0) ---
        unsigned pownA[2][4];
        s_exp(KuA, pownA);
        px[((px_base + h) * 2 + 0) * 32 + lane] =
            make_uint4(pownA[0][0], pownA[0][1], pownA[0][2], pownA[0][3]);
        px[((px_base + h) * 2 + 1) * 32 + lane] =
            make_uint4(pownA[1][0], pownA[1][1], pownA[1][2], pownA[1][3]);

        // --- own PV A (hides exchange A) ---
        own_pv(vlaneA, pownA);

        // --- tile B: S, exp, publish (set 1) — fills PV_A's latency gaps ---
        unsigned pownB[2][4];
        s_exp(KuB, pownB);
        px[1024 + ((px_base + h) * 2 + 0) * 32 + lane] =
            make_uint4(pownB[0][0], pownB[0][1], pownB[0][2], pownB[0][3]);
        px[1024 + ((px_base + h) * 2 + 1) * 32 + lane] =
            make_uint4(pownB[1][0], pownB[1][1], pownB[1][2], pownB[1][3]);

        // --- ONE named barrier covers both publishes (4 warps sharing r) ---
        asm volatile("bar.sync %0, %1;" :: "r"(r + 1), "r"(128) : "memory");

        partner_pv(vlaneA, 0);
        own_pv(vlaneB, pownB);
        partner_pv(vlaneB, 1);
    }

    // ---- reduce l: quad, then across 4 h via smem ----
#pragma unroll
    for (int rg = 0; rg < 2; rg++)
#pragma unroll
        for (int i = 0; i < 2; i++) {
            lr[rg][i] += __shfl_xor_sync(0xffffffffu, lr[rg][i], 1);
            lr[rg][i] += __shfl_xor_sync(0xffffffffu, lr[rg][i], 2);
        }

    float* ls = (float*)(smc + SM_LS_OFF);
    __syncthreads();
    if (t4 == 0) {
#pragma unroll
        for (int rg = 0; rg < 2; rg++) {
            ls[h * 128 + row0 + 16 * rg]     = lr[rg][0];
            ls[h * 128 + row0 + 16 * rg + 8] = lr[rg][1];
        }
    }
    __syncthreads();

    float il[2][2];
#pragma unroll
    for (int rg = 0; rg < 2; rg++)
#pragma unroll
        for (int i = 0; i < 2; i++) {
            int row = row0 + 16 * rg + 8 * i;
            float lt = ls[row] + ls[128 + row] + ls[256 + row] + ls[384 + row];
            il[rg][i] = 1.0f / lt;
        }

    // ---- epilogue: out = gamma * O / l + x ----
    float gm = gamma[0];
#pragma unroll
    for (int cb = 0; cb < 8; cb++) {
        int c = 64 * h + 8 * cb + 2 * t4;
#pragma unroll
        for (int rg = 0; rg < 2; rg++) {
            int n = n0 + row0 + 16 * rg;
            size_t i00 = ((size_t)(b * CIN + c)) * NPIX + n;
            out[i00]            = gm * (O[cb][rg][0] * il[rg][0]) + x[i00];
            out[i00 + NPIX]     = gm * (O[cb][rg][1] * il[rg][0]) + x[i00 + NPIX];
            out[i00 + 8]        = gm * (O[cb][rg][2] * il[rg][1]) + x[i00 + 8];
            out[i00 + NPIX + 8] = gm * (O[cb][rg][3] * il[rg][1]) + x[i00 + NPIX + 8];
        }
    }
}

// ---------------------------------------------------------------------------
extern "C" void kernel_launch(void* const* d_in, const int* in_sizes, int n_in,
                              void* d_out, int out_size)
{
    (void)in_sizes; (void)n_in; (void)out_size;
    const float* x     = (const float*)d_in[0];
    const float* Wq    = (const float*)d_in[1];
    const float* bq    = (const float*)d_in[2];
    const float* Wk    = (const float*)d_in[3];
    const float* bk    = (const float*)d_in[4];
    const float* Wv    = (const float*)d_in[5];
    const float* bv    = (const float*)d_in[6];
    const float* gamma = (const float*)d_in[7];
    float* out = (float*)d_out;

    cudaFuncSetAttribute(proj_kernel,
                         cudaFuncAttributeMaxDynamicSharedMemorySize, P_TOTAL);
    cudaFuncSetAttribute(attn_kernel,
                         cudaFuncAttributeMaxDynamicSharedMemorySize, SM_TOTAL);

    proj_kernel<<<dim3(NPIX / 128, 5, NB), 256, P_TOTAL>>>(x, Wq, bq, Wk, bk, Wv, bv);
    attn_kernel<<<dim3(NPIX / 128, NB), 512, SM_TOTAL>>>(x, gamma, out);
}

// round 17
// speedup vs baseline: 1.0878x; 1.0878x over previous
#include <cuda_runtime.h>
#include <cuda_bf16.h>
#include <math.h>
#include <stdint.h>

#define NB   4
#define CIN  256
#define C8D  32
#define NPIX 4096

// Scratch (device globals: allocation-free per harness rules).
__device__ float g_q[NB * C8D * NPIX];          // tf32-rounded
__device__ float g_k[NB * C8D * NPIX];          // tf32-rounded
__device__ __nv_bfloat16 g_v[NB * CIN * NPIX];  // bf16

__device__ __forceinline__ unsigned f2tf32(float x) {
    unsigned u;
    asm("cvt.rna.tf32.f32 %0, %1;" : "=r"(u) : "f"(x));
    return u;
}

__device__ __forceinline__ void mma_tf32(float* d, const unsigned* a, const unsigned* b) {
    asm volatile(
        "mma.sync.aligned.m16n8k8.row.col.f32.tf32.tf32.f32 "
        "{%0,%1,%2,%3}, {%4,%5,%6,%7}, {%8,%9}, {%0,%1,%2,%3};"
        : "+f"(d[0]), "+f"(d[1]), "+f"(d[2]), "+f"(d[3])
        : "r"(a[0]), "r"(a[1]), "r"(a[2]), "r"(a[3]), "r"(b[0]), "r"(b[1]));
}

__device__ __forceinline__ void mma_bf16(float* d, const unsigned* a, unsigned b0, unsigned b1) {
    asm volatile(
        "mma.sync.aligned.m16n8k16.row.col.f32.bf16.bf16.f32 "
        "{%0,%1,%2,%3}, {%4,%5,%6,%7}, {%8,%9}, {%0,%1,%2,%3};"
        : "+f"(d[0]), "+f"(d[1]), "+f"(d[2]), "+f"(d[3])
        : "r"(a[0]), "r"(a[1]), "r"(a[2]), "r"(a[3]), "r"(b0), "r"(b1));
}

__device__ __forceinline__ unsigned pack_bf16(float lo, float hi) {
    __nv_bfloat162 p = __floats2bfloat162_rn(lo, hi);
    return *(unsigned*)&p;
}

__device__ __forceinline__ void cp16(unsigned dst, const void* src) {
    asm volatile("cp.async.cg.shared.global [%0], [%1], 16;\n" :: "r"(dst), "l"(src));
}

__device__ __forceinline__ void ldsm_x4(unsigned& r0, unsigned& r1, unsigned& r2, unsigned& r3,
                                        unsigned addr) {
    asm volatile("ldmatrix.sync.aligned.m8n8.x4.shared.b16 {%0,%1,%2,%3}, [%4];"
                 : "=r"(r0), "=r"(r1), "=r"(r2), "=r"(r3) : "r"(addr));
}

// ---------------------------------------------------------------------------
// Merged projection GEMM on tf32 mma (unchanged — measured ~27us).
// ---------------------------------------------------------------------------
#define PW_S 36
#define PX_S 136
#define P_WBUF (64 * PW_S * 4)
#define P_XOFF (2 * P_WBUF)
#define P_XBUF (32 * PX_S * 4)
#define P_TOTAL (P_XOFF + 2 * P_XBUF)

__global__ __launch_bounds__(256) void proj_kernel(
    const float* __restrict__ x,
    const float* __restrict__ Wq, const float* __restrict__ bq,
    const float* __restrict__ Wk, const float* __restrict__ bk,
    const float* __restrict__ Wv, const float* __restrict__ bv)
{
    extern __shared__ char smc[];
    unsigned sm_base = (unsigned)__cvta_generic_to_shared(smc);

    int b  = blockIdx.z;
    int r0 = blockIdx.y * 64;
    int n0 = blockIdx.x * 128;
    int t  = threadIdx.x;
    int w = t >> 5, lane = t & 31;
    int g = lane >> 2, t4 = lane & 3;
    int wr = w & 3, wc = w >> 2;
    const float* xb = x + ((size_t)b * CIN) * NPIX;

    auto wrow = [&](int gr) -> const float* {
        return (gr < 256) ? (Wv + (size_t)gr * 256)
             : (gr < 288) ? (Wq + (size_t)(gr - 256) * 256)
                          : (Wk + (size_t)(gr - 288) * 256);
    };

    auto issue_stage = [&](int ch) {
        int k0 = ch * 32;
        unsigned wdst = sm_base + (unsigned)(ch & 1) * P_WBUF;
#pragma unroll
        for (int i = 0; i < 2; i++) {
            int idx = t + 256 * i;
            int row = idx >> 3, seg = idx & 7;
            cp16(wdst + (unsigned)(row * PW_S + seg * 4) * 4,
                 wrow(r0 + row) + k0 + seg * 4);
        }
        unsigned xdst = sm_base + P_XOFF + (unsigned)(ch & 1) * P_XBUF;
#pragma unroll
        for (int i = 0; i < 4; i++) {
            int idx = t + 256 * i;
            int row = idx >> 5, seg = idx & 31;
            cp16(xdst + (unsigned)(row * PX_S + seg * 4) * 4,
                 xb + (size_t)(k0 + row) * NPIX + n0 + seg * 4);
        }
        asm volatile("cp.async.commit_group;\n");
    };

    issue_stage(0);

    float acc[8][4];
#pragma unroll
    for (int jb = 0; jb < 8; jb++)
#pragma unroll
        for (int q = 0; q < 4; q++) acc[jb][q] = 0.0f;

    for (int ch = 0; ch < 8; ch++) {
        asm volatile("cp.async.wait_group 0;\n");
        __syncthreads();
        if (ch + 1 < 8) issue_stage(ch + 1);

        const unsigned* Wu = (const unsigned*)(smc + (ch & 1) * P_WBUF);
        const unsigned* Xu = (const unsigned*)(smc + P_XOFF + (ch & 1) * P_XBUF);

#pragma unroll
        for (int ks = 0; ks < 4; ks++) {
            int kk = 8 * ks;
            unsigned a[4];
            a[0] = Wu[(16 * wr + g)     * PW_S + kk + t4];
            a[1] = Wu[(16 * wr + g + 8) * PW_S + kk + t4];
            a[2] = Wu[(16 * wr + g)     * PW_S + kk + t4 + 4];
            a[3] = Wu[(16 * wr + g + 8) * PW_S + kk + t4 + 4];
#pragma unroll
            for (int jb = 0; jb < 8; jb++) {
                unsigned bfr[2];
                bfr[0] = Xu[(kk + t4)     * PX_S + 64 * wc + 8 * jb + g];
                bfr[1] = Xu[(kk + t4 + 4) * PX_S + 64 * wc + 8 * jb + g];
                mma_tf32(acc[jb], a, bfr);
            }
        }
        __syncthreads();
    }

    int gr0 = r0 + 16 * wr + g;
    int gr1 = gr0 + 8;
#pragma unroll
    for (int half = 0; half < 2; half++) {
        int gr = half ? gr1 : gr0;
        if (gr < 256) {
            float bias = bv[gr];
            __nv_bfloat16* op = g_v + ((size_t)b * CIN + gr) * NPIX;
#pragma unroll
            for (int jb = 0; jb < 8; jb++) {
                int c0 = n0 + 64 * wc + 8 * jb + 2 * t4;
                float d0 = acc[jb][half ? 2 : 0] + bias;
                float d1 = acc[jb][half ? 3 : 1] + bias;
                *(unsigned*)&op[c0] = pack_bf16(d0, d1);
            }
        } else {
            float bias;
            float* op;
            if (gr < 288) { bias = bq[gr - 256]; op = g_q + ((size_t)b * C8D + gr - 256) * NPIX; }
            else          { bias = bk[gr - 288]; op = g_k + ((size_t)b * C8D + gr - 288) * NPIX; }
#pragma unroll
            for (int jb = 0; jb < 8; jb++) {
                int c0 = n0 + 64 * wc + 8 * jb + 2 * t4;
                float2 o;
                o.x = __uint_as_float(f2tf32(acc[jb][half ? 2 : 0] + bias));
                o.y = __uint_as_float(f2tf32(acc[jb][half ? 3 : 1] + bias));
                *(float2*)&op[c0] = o;
            }
        }
    }
}

// ---------------------------------------------------------------------------
// Flash attention, 4r x 4h tile (R14 body) + RELAXED SYNC CADENCE:
// __syncthreads only on EVEN iterations; K/V x4 buffers staged at mt+2
// (wait_group 1); P-exchange double-set (mt&1) so odd iterations need no
// block-wide realignment -> r-groups drift and overlap S/exp/PV phases.
// Per-iteration body identical to R14 (register pressure unchanged).
// ---------------------------------------------------------------------------
#define KS_S 72   // floats
#define VS_S 72   // bf16 units (144 B per row)
#define SM_K_BUF  (32 * KS_S * 4)             // 9216 B
#define SM_V_OFF  (4 * SM_K_BUF)              // 36864
#define SM_V_BUF  (256 * VS_S * 2)            // 36864 B
#define SM_PX_OFF (SM_V_OFF + 4 * SM_V_BUF)   // 184320 (2 sets x 16384)
#define SM_LS_OFF (SM_PX_OFF + 32768)         // 217088
#define SM_TOTAL  (SM_LS_OFF + 2048)          // 219136 B (1 CTA/SM)

__global__ __launch_bounds__(512, 1) void attn_kernel(
    const float* __restrict__ x, const float* __restrict__ gamma,
    float* __restrict__ out)
{
    extern __shared__ char smc[];
    unsigned sm_base = (unsigned)__cvta_generic_to_shared(smc);

    int t = threadIdx.x;
    int w = t >> 5, lane = t & 31;
    int g = lane >> 2, t4 = lane & 3;
    int r = w & 3;        // query rows [32r, 32r+32)
    int h = w >> 2;       // c quarter AND key quarter
    int b = blockIdx.y;
    int n0 = blockIdx.x * 128;

    const float* qb = g_q + ((size_t)b * C8D) * NPIX;
    const float* kb = g_k + ((size_t)b * C8D) * NPIX;
    const __nv_bfloat16* vbb = g_v + ((size_t)b * CIN) * NPIX;

    auto issue_tile = [&](int tile) {
        int m0 = tile * 64;
        unsigned kdst = sm_base + (unsigned)(tile & 3) * SM_K_BUF;
        {   // K: 512 x 16B, one per thread
            int d = t >> 4, seg = t & 15;
            cp16(kdst + (unsigned)(d * KS_S + seg * 4) * 4,
                 kb + (size_t)d * NPIX + m0 + seg * 4);
        }
        unsigned vdst = sm_base + SM_V_OFF + (unsigned)(tile & 3) * SM_V_BUF;
#pragma unroll
        for (int i = 0; i < 4; i++) {   // V: 2048 x 16B
            int flat = t + 512 * i;
            int c = flat >> 3, seg = flat & 7;
            cp16(vdst + (unsigned)(c * VS_S + seg * 8) * 2,
                 vbb + (size_t)c * NPIX + m0 + seg * 8);
        }
        asm volatile("cp.async.commit_group;\n");
    };

    // prologue: two tiles in flight
    issue_tile(0);
    issue_tile(1);

    const int row0 = 32 * r + g;      // rowgroup 0 base; rowgroup 1 = +16

    // Q fragments (loop-invariant, 32 regs)
    unsigned qa[4][2][4];
#pragma unroll
    for (int ks = 0; ks < 4; ks++) {
        int d0 = 8 * ks + t4;
#pragma unroll
        for (int rg = 0; rg < 2; rg++) {
            int rr = row0 + 16 * rg;
            qa[ks][rg][0] = __float_as_uint(qb[(size_t)d0 * NPIX + n0 + rr]);
            qa[ks][rg][1] = __float_as_uint(qb[(size_t)d0 * NPIX + n0 + rr + 8]);
            qa[ks][rg][2] = __float_as_uint(qb[(size_t)(d0 + 4) * NPIX + n0 + rr]);
            qa[ks][rg][3] = __float_as_uint(qb[(size_t)(d0 + 4) * NPIX + n0 + rr + 8]);
        }
    }

    unsigned laneoff = (unsigned)((8 * (lane >> 4) + (lane & 7)) * (VS_S * 2)
                                  + ((lane >> 3) & 1) * 16);
    unsigned vlane_base = sm_base + SM_V_OFF + (unsigned)(h * 64 * VS_S * 2) + laneoff;

    uint4* px = (uint4*)(smc + SM_PX_OFF);
    int px_base = r * 4;

    float O[8][2][4];
#pragma unroll
    for (int cb = 0; cb < 8; cb++)
#pragma unroll
        for (int rg = 0; rg < 2; rg++)
#pragma unroll
            for (int q = 0; q < 4; q++) O[cb][rg][q] = 0.0f;

    float lr[2][2] = {{0.0f, 0.0f}, {0.0f, 0.0f}};

    for (int mt = 0; mt < 64; mt++) {
        if (mt < 62) {
            asm volatile("cp.async.wait_group 1;\n");
        } else {
            asm volatile("cp.async.wait_group 0;\n");
        }
        if ((mt & 1) == 0) __syncthreads();
        if (mt + 2 < 64) issue_tile(mt + 2);

        const unsigned* Ku = (const unsigned*)(smc + (mt & 3) * SM_K_BUF);
        int set = (mt & 1) * 1024;   // px set offset (uint4 units)

        // ---- S (tf32): 2 rowgroups x key quarter [16h,16h+16) ----
        float S[2][2][4];
#pragma unroll
        for (int rg = 0; rg < 2; rg++)
#pragma unroll
            for (int j = 0; j < 2; j++)
#pragma unroll
                for (int q = 0; q < 4; q++) S[rg][j][q] = 0.0f;
#pragma unroll
        for (int ks = 0; ks < 4; ks++) {
            int kk = 8 * ks;
#pragma unroll
            for (int j = 0; j < 2; j++) {
                int jj = 2 * h + j;
                unsigned bfr[2];
                bfr[0] = Ku[(kk + t4)     * KS_S + 8 * jj + g];
                bfr[1] = Ku[(kk + t4 + 4) * KS_S + 8 * jj + g];
#pragma unroll
                for (int rg = 0; rg < 2; rg++)
                    mma_tf32(S[rg][j], qa[ks][rg], bfr);
            }
        }

        // ---- P = exp(S): one k16 A-frag group per rowgroup ----
        unsigned pown[2][4];
#pragma unroll
        for (int rg = 0; rg < 2; rg++) {
#pragma unroll
            for (int j = 0; j < 2; j++) {
                float p00 = __expf(S[rg][j][0]);
                float p01 = __expf(S[rg][j][1]);
                float p10 = __expf(S[rg][j][2]);
                float p11 = __expf(S[rg][j][3]);
                lr[rg][0] += p00 + p01;
                lr[rg][1] += p10 + p11;
                if (j == 0) {
                    pown[rg][0] = pack_bf16(p00, p01);
                    pown[rg][1] = pack_bf16(p10, p11);
                } else {
                    pown[rg][2] = pack_bf16(p00, p01);
                    pown[rg][3] = pack_bf16(p10, p11);
                }
            }
        }

        // publish own P frag groups (set mt&1)
        px[set + ((px_base + h) * 2 + 0) * 32 + lane] =
            make_uint4(pown[0][0], pown[0][1], pown[0][2], pown[0][3]);
        px[set + ((px_base + h) * 2 + 1) * 32 + lane] =
            make_uint4(pown[1][0], pown[1][1], pown[1][2], pown[1][3]);

        unsigned vlane = vlane_base + (unsigned)(mt & 3) * SM_V_BUF;

        // ---- own-kc PV first (hides exchange) ----
#pragma unroll
        for (int p = 0; p < 4; p++) {
            unsigned b0, b1, b2, b3;
            ldsm_x4(b0, b1, b2, b3,
                    vlane + (unsigned)(p * 16 * VS_S * 2) + (unsigned)(h * 32));
#pragma unroll
            for (int rg = 0; rg < 2; rg++) {
                mma_bf16(O[2 * p][rg],     pown[rg], b0, b1);
                mma_bf16(O[2 * p + 1][rg], pown[rg], b2, b3);
            }
        }

        // ---- barrier over the 4 warps sharing r, then 3 partner kc ----
        asm volatile("bar.sync %0, %1;" :: "r"(r + 1), "r"(128) : "memory");
#pragma unroll
        for (int dk = 1; dk < 4; dk++) {
            int kc = (h + dk) & 3;
            uint4 pp0 = px[set + ((px_base + kc) * 2 + 0) * 32 + lane];
            uint4 pp1 = px[set + ((px_base + kc) * 2 + 1) * 32 + lane];
            unsigned pfr[2][4] = {
                {pp0.x, pp0.y, pp0.z, pp0.w},
                {pp1.x, pp1.y, pp1.z, pp1.w}
            };
#pragma unroll
            for (int p = 0; p < 4; p++) {
                unsigned b0, b1, b2, b3;
                ldsm_x4(b0, b1, b2, b3,
                        vlane + (unsigned)(p * 16 * VS_S * 2) + (unsigned)(kc * 32));
#pragma unroll
                for (int rg = 0; rg < 2; rg++) {
                    mma_bf16(O[2 * p][rg],     pfr[rg], b0, b1);
                    mma_bf16(O[2 * p + 1][rg], pfr[rg], b2, b3);
                }
            }
        }
    }

    // ---- reduce l: quad, then across 4 h via smem ----
#pragma unroll
    for (int rg = 0; rg < 2; rg++)
#pragma unroll
        for (int i = 0; i < 2; i++) {
            lr[rg][i] += __shfl_xor_sync(0xffffffffu, lr[rg][i], 1);
            lr[rg][i] += __shfl_xor_sync(0xffffffffu, lr[rg][i], 2);
        }

    float* ls = (float*)(smc + SM_LS_OFF);
    __syncthreads();
    if (t4 == 0) {
#pragma unroll
        for (int rg = 0; rg < 2; rg++) {
            ls[h * 128 + row0 + 16 * rg]     = lr[rg][0];
            ls[h * 128 + row0 + 16 * rg + 8] = lr[rg][1];
        }
    }
    __syncthreads();

    float il[2][2];
#pragma unroll
    for (int rg = 0; rg < 2; rg++)
#pragma unroll
        for (int i = 0; i < 2; i++) {
            int row = row0 + 16 * rg + 8 * i;
            float lt = ls[row] + ls[128 + row] + ls[256 + row] + ls[384 + row];
            il[rg][i] = 1.0f / lt;
        }

    // ---- epilogue: out = gamma * O / l + x ----
    float gm = gamma[0];
#pragma unroll
    for (int cb = 0; cb < 8; cb++) {
        int c = 64 * h + 8 * cb + 2 * t4;
#pragma unroll
        for (int rg = 0; rg < 2; rg++) {
            int n = n0 + row0 + 16 * rg;
            size_t i00 = ((size_t)(b * CIN + c)) * NPIX + n;
            out[i00]            = gm * (O[cb][rg][0] * il[rg][0]) + x[i00];
            out[i00 + NPIX]     = gm * (O[cb][rg][1] * il[rg][0]) + x[i00 + NPIX];
            out[i00 + 8]        = gm * (O[cb][rg][2] * il[rg][1]) + x[i00 + 8];
            out[i00 + NPIX + 8] = gm * (O[cb][rg][3] * il[rg][1]) + x[i00 + NPIX + 8];
        }
    }
}

// ---------------------------------------------------------------------------
extern "C" void kernel_launch(void* const* d_in, const int* in_sizes, int n_in,
                              void* d_out, int out_size)
{
    (void)in_sizes; (void)n_in; (void)out_size;
    const float* x     = (const float*)d_in[0];
    const float* Wq    = (const float*)d_in[1];
    const float* bq    = (const float*)d_in[2];
    const float* Wk    = (const float*)d_in[3];
    const float* bk    = (const float*)d_in[4];
    const float* Wv    = (const float*)d_in[5];
    const float* bv    = (const float*)d_in[6];
    const float* gamma = (const float*)d_in[7];
    float* out = (float*)d_out;

    cudaFuncSetAttribute(proj_kernel,
                         cudaFuncAttributeMaxDynamicSharedMemorySize, P_TOTAL);
    cudaFuncSetAttribute(attn_kernel,
                         cudaFuncAttributeMaxDynamicSharedMemorySize, SM_TOTAL);

    proj_kernel<<<dim3(NPIX / 128, 5, NB), 256, P_TOTAL>>>(x, Wq, bq, Wk, bk, Wv, bv);
    attn_kernel<<<dim3(NPIX / 128, NB), 512, SM_TOTAL>>>(x, gamma, out);
}